// round 1
// baseline (speedup 1.0000x reference)
#include <cuda_runtime.h>
#include <cuda_bf16.h>
#include <cstdint>

// Problem constants (fixed by setup_inputs)
#define N_TOK 16384
#define DIM   128
#define BM    128          // rows per CTA
#define BN    64           // keys per iteration
#define NITER (N_TOK / BN) // 256
#define NBLK  (N_TOK / BM) // 128 CTAs

// SMEM layout (halves): padded strides give +4-bank shift per row -> conflict-free ldmatrix
#define QSTRIDE 136        // 128 cols + 8 pad (272B row, 68 banks -> shift 4)
#define KSTRIDE 136
#define VSTRIDE 72         // 64 cols + 8 pad (144B row -> shift 4)

#define Q_BYTES (BM * QSTRIDE * 2)   // 34816
#define K_BYTES (BN * KSTRIDE * 2)   // 17408
#define V_BYTES (DIM * VSTRIDE * 2)  // 18432
#define OFF_K0  (Q_BYTES)
#define OFF_K1  (OFF_K0 + K_BYTES)
#define OFF_V0  (OFF_K1 + K_BYTES)
#define OFF_V1  (OFF_V0 + V_BYTES)
#define SMEM_TOTAL (OFF_V1 + V_BYTES) // 106496

// Scratch in static device memory (no allocations allowed)
__device__ __nv_bfloat16 g_nx[N_TOK * DIM]; // row-normalized x, bf16 (Q and K)
__device__ __nv_bfloat16 g_xT[DIM * N_TOK]; // x transposed, bf16 (V, feature-major)

// ---------------------------------------------------------------------------
// helpers
// ---------------------------------------------------------------------------
__device__ __forceinline__ uint32_t sptr(const void* p) {
    return (uint32_t)__cvta_generic_to_shared(p);
}

__device__ __forceinline__ void cp16(uint32_t dst, const void* src) {
    asm volatile("cp.async.cg.shared.global [%0], [%1], 16;\n" :: "r"(dst), "l"(src));
}

__device__ __forceinline__ void ldm4(uint32_t r[4], uint32_t addr) {
    asm volatile("ldmatrix.sync.aligned.m8n8.x4.shared.b16 {%0,%1,%2,%3}, [%4];\n"
                 : "=r"(r[0]), "=r"(r[1]), "=r"(r[2]), "=r"(r[3]) : "r"(addr));
}

__device__ __forceinline__ void mma16816(float c[4],
                                         uint32_t a0, uint32_t a1, uint32_t a2, uint32_t a3,
                                         uint32_t b0, uint32_t b1) {
    asm volatile(
        "mma.sync.aligned.m16n8k16.row.col.f32.bf16.bf16.f32 "
        "{%0,%1,%2,%3},{%4,%5,%6,%7},{%8,%9},{%0,%1,%2,%3};\n"
        : "+f"(c[0]), "+f"(c[1]), "+f"(c[2]), "+f"(c[3])
        : "r"(a0), "r"(a1), "r"(a2), "r"(a3), "r"(b0), "r"(b1));
}

__device__ __forceinline__ uint32_t pack_bf16x2(float lo, float hi) {
    __nv_bfloat162 h = __floats2bfloat162_rn(lo, hi); // .x = lo (low 16 bits)
    return *reinterpret_cast<uint32_t*>(&h);
}

// ---------------------------------------------------------------------------
// Kernel 1: row norms -> g_nx (bf16), and transposed bf16 copy -> g_xT
// one warp per row, 8 rows per 256-thread block
// ---------------------------------------------------------------------------
__global__ void __launch_bounds__(256) prep_kernel(const float* __restrict__ x) {
    const int warp = threadIdx.x >> 5;
    const int lane = threadIdx.x & 31;
    const int row  = blockIdx.x * 8 + warp;

    const float4 v = reinterpret_cast<const float4*>(x)[row * (DIM / 4) + lane];
    float ss = v.x * v.x + v.y * v.y + v.z * v.z + v.w * v.w;
    #pragma unroll
    for (int off = 16; off > 0; off >>= 1)
        ss += __shfl_xor_sync(0xffffffffu, ss, off);
    const float scale = 1.0f / fmaxf(sqrtf(ss), 1e-12f);

    // normalized, bf16
    __nv_bfloat162* nx2 = reinterpret_cast<__nv_bfloat162*>(g_nx);
    nx2[row * (DIM / 2) + lane * 2 + 0] = __floats2bfloat162_rn(v.x * scale, v.y * scale);
    nx2[row * (DIM / 2) + lane * 2 + 1] = __floats2bfloat162_rn(v.z * scale, v.w * scale);

    // transposed raw x, bf16 (scattered 2B stores; everything lives in L2)
    const int c = lane * 4;
    g_xT[(c + 0) * N_TOK + row] = __float2bfloat16(v.x);
    g_xT[(c + 1) * N_TOK + row] = __float2bfloat16(v.y);
    g_xT[(c + 2) * N_TOK + row] = __float2bfloat16(v.z);
    g_xT[(c + 3) * N_TOK + row] = __float2bfloat16(v.w);
}

// ---------------------------------------------------------------------------
// Kernel 2: streaming attention + fused epilogue
// 128 CTAs x 256 threads (8 warps). Warp tile: 16 rows x 64 keys for S,
// 16 rows x 128 features for O (k=64 fully warp-local -> P reused from regs).
// ---------------------------------------------------------------------------
__global__ void __launch_bounds__(256, 1) attn_kernel(
    const float* __restrict__ x,
    const float* __restrict__ gamma,
    const float* __restrict__ beta,
    float* __restrict__ out)
{
    extern __shared__ char smem[];
    const uint32_t sQ = sptr(smem);
    const int tid  = threadIdx.x;
    const int lane = tid & 31;
    const int warp = tid >> 5;
    const int row0 = blockIdx.x * BM;

    // ---- prologue: Q tile + stage 0 (group 0) ----
    {
        const __nv_bfloat16* nx = g_nx;
        #pragma unroll
        for (int j = 0; j < 8; j++) {                 // 128 rows x 16 chunks
            int idx = tid + j * 256;
            int r = idx >> 4, c = idx & 15;
            cp16(sQ + (uint32_t)(r * QSTRIDE + c * 8) * 2,
                 nx + (size_t)(row0 + r) * DIM + c * 8);
        }
        #pragma unroll
        for (int j = 0; j < 4; j++) {                 // K stage 0: 64 rows x 16 chunks
            int idx = tid + j * 256;
            int r = idx >> 4, c = idx & 15;
            cp16(sQ + OFF_K0 + (uint32_t)(r * KSTRIDE + c * 8) * 2,
                 nx + (size_t)r * DIM + c * 8);
        }
        #pragma unroll
        for (int j = 0; j < 4; j++) {                 // V stage 0: 128 rows x 8 chunks
            int idx = tid + j * 256;
            int r = idx >> 3, c = idx & 7;
            cp16(sQ + OFF_V0 + (uint32_t)(r * VSTRIDE + c * 8) * 2,
                 g_xT + (size_t)r * N_TOK + c * 8);
        }
        asm volatile("cp.async.commit_group;\n");
    }

    // fragment address components (shared by K and V ldmatrix)
    const uint32_t a_row  = warp * 16 + (lane & 15);
    const uint32_t a_coff = ((lane >> 4) & 1) * 8;
    const uint32_t b_roff = (lane & 7) + ((lane >> 4) & 1) * 8;
    const uint32_t b_coff = ((lane >> 3) & 1) * 8;

    float o[16][4];
    #pragma unroll
    for (int i = 0; i < 16; i++)
        #pragma unroll
        for (int j = 0; j < 4; j++) o[i][j] = 0.0f;
    float sum_lo = 0.0f, sum_hi = 0.0f;

    for (int kb = 0; kb < NITER; kb++) {
        // ---- issue next stage into the other buffer ----
        if (kb + 1 < NITER) {
            const int s = (kb + 1) & 1;
            const int key0 = (kb + 1) * BN;
            const uint32_t kb_off = s ? OFF_K1 : OFF_K0;
            const uint32_t vb_off = s ? OFF_V1 : OFF_V0;
            #pragma unroll
            for (int j = 0; j < 4; j++) {
                int idx = tid + j * 256;
                int r = idx >> 4, c = idx & 15;
                cp16(sQ + kb_off + (uint32_t)(r * KSTRIDE + c * 8) * 2,
                     g_nx + (size_t)(key0 + r) * DIM + c * 8);
            }
            #pragma unroll
            for (int j = 0; j < 4; j++) {
                int idx = tid + j * 256;
                int r = idx >> 3, c = idx & 7;
                cp16(sQ + vb_off + (uint32_t)(r * VSTRIDE + c * 8) * 2,
                     g_xT + (size_t)r * N_TOK + key0 + c * 8);
            }
            asm volatile("cp.async.commit_group;\n");
            asm volatile("cp.async.wait_group 1;\n");
        } else {
            asm volatile("cp.async.wait_group 0;\n");
        }
        __syncthreads();

        const int s = kb & 1;
        const uint32_t kbase = sQ + (s ? OFF_K1 : OFF_K0);
        const uint32_t vbase = sQ + (s ? OFF_V1 : OFF_V0);

        // ---- S = Q @ K^T (16x64 per warp, k=128) ----
        float sacc[8][4];
        #pragma unroll
        for (int i = 0; i < 8; i++)
            #pragma unroll
            for (int j = 0; j < 4; j++) sacc[i][j] = 0.0f;

        #pragma unroll
        for (int k = 0; k < 8; k++) {
            const int k16 = k * 16;
            uint32_t A[4];
            ldm4(A, sQ + (uint32_t)(a_row * QSTRIDE + k16 + a_coff) * 2);
            #pragma unroll
            for (int ntp = 0; ntp < 4; ntp++) {
                const int n0 = ntp * 16;
                uint32_t B[4];
                ldm4(B, kbase + (uint32_t)((n0 + b_roff) * KSTRIDE + k16 + b_coff) * 2);
                mma16816(sacc[2 * ntp + 0], A[0], A[1], A[2], A[3], B[0], B[1]);
                mma16816(sacc[2 * ntp + 1], A[0], A[1], A[2], A[3], B[2], B[3]);
            }
        }

        // ---- P = exp(S) (no max needed: S in [-1,1]); pack to bf16 A-fragments ----
        uint32_t p[8][2];
        #pragma unroll
        for (int nt = 0; nt < 8; nt++) {
            const float e0 = __expf(sacc[nt][0]);
            const float e1 = __expf(sacc[nt][1]);
            const float e2 = __expf(sacc[nt][2]);
            const float e3 = __expf(sacc[nt][3]);
            sum_lo += e0 + e1;
            sum_hi += e2 + e3;
            p[nt][0] = pack_bf16x2(e0, e1);
            p[nt][1] = pack_bf16x2(e2, e3);
        }

        // ---- O += P @ V (16x128 per warp, k=64, A from registers) ----
        #pragma unroll
        for (int kk = 0; kk < 4; kk++) {
            const uint32_t A0 = p[2 * kk + 0][0];
            const uint32_t A1 = p[2 * kk + 0][1];
            const uint32_t A2 = p[2 * kk + 1][0];
            const uint32_t A3 = p[2 * kk + 1][1];
            #pragma unroll
            for (int vp = 0; vp < 8; vp++) {
                const int n0 = vp * 16;
                uint32_t B[4];
                ldm4(B, vbase + (uint32_t)((n0 + b_roff) * VSTRIDE + kk * 16 + b_coff) * 2);
                mma16816(o[2 * vp + 0], A0, A1, A2, A3, B[0], B[1]);
                mma16816(o[2 * vp + 1], A0, A1, A2, A3, B[2], B[3]);
            }
        }
        __syncthreads();
    }

    // ---- fused epilogue: /rowsum, y = 1.5x - 0.5 x_neg, LayerNorm ----
    sum_lo += __shfl_xor_sync(0xffffffffu, sum_lo, 1);
    sum_lo += __shfl_xor_sync(0xffffffffu, sum_lo, 2);
    sum_hi += __shfl_xor_sync(0xffffffffu, sum_hi, 1);
    sum_hi += __shfl_xor_sync(0xffffffffu, sum_hi, 2);
    const float inv_lo = 1.0f / sum_lo;
    const float inv_hi = 1.0f / sum_hi;

    const int g = lane >> 2;
    const int t = lane & 3;
    const int row_lo = row0 + warp * 16 + g;
    const int row_hi = row_lo + 8;
    const float* xr_lo = x + (size_t)row_lo * DIM;
    const float* xr_hi = x + (size_t)row_hi * DIM;

    float msum_lo = 0.0f, msum_hi = 0.0f;
    #pragma unroll
    for (int nt = 0; nt < 16; nt++) {
        const int c0 = nt * 8 + t * 2;
        o[nt][0] = 1.5f * xr_lo[c0]     - 0.5f * o[nt][0] * inv_lo;
        o[nt][1] = 1.5f * xr_lo[c0 + 1] - 0.5f * o[nt][1] * inv_lo;
        o[nt][2] = 1.5f * xr_hi[c0]     - 0.5f * o[nt][2] * inv_hi;
        o[nt][3] = 1.5f * xr_hi[c0 + 1] - 0.5f * o[nt][3] * inv_hi;
        msum_lo += o[nt][0] + o[nt][1];
        msum_hi += o[nt][2] + o[nt][3];
    }
    msum_lo += __shfl_xor_sync(0xffffffffu, msum_lo, 1);
    msum_lo += __shfl_xor_sync(0xffffffffu, msum_lo, 2);
    msum_hi += __shfl_xor_sync(0xffffffffu, msum_hi, 1);
    msum_hi += __shfl_xor_sync(0xffffffffu, msum_hi, 2);
    const float mu_lo = msum_lo * (1.0f / DIM);
    const float mu_hi = msum_hi * (1.0f / DIM);

    float vs_lo = 0.0f, vs_hi = 0.0f;
    #pragma unroll
    for (int nt = 0; nt < 16; nt++) {
        float d0 = o[nt][0] - mu_lo, d1 = o[nt][1] - mu_lo;
        float d2 = o[nt][2] - mu_hi, d3 = o[nt][3] - mu_hi;
        vs_lo += d0 * d0 + d1 * d1;
        vs_hi += d2 * d2 + d3 * d3;
    }
    vs_lo += __shfl_xor_sync(0xffffffffu, vs_lo, 1);
    vs_lo += __shfl_xor_sync(0xffffffffu, vs_lo, 2);
    vs_hi += __shfl_xor_sync(0xffffffffu, vs_hi, 1);
    vs_hi += __shfl_xor_sync(0xffffffffu, vs_hi, 2);
    const float rstd_lo = rsqrtf(vs_lo * (1.0f / DIM) + 1e-5f);
    const float rstd_hi = rsqrtf(vs_hi * (1.0f / DIM) + 1e-5f);

    float* or_lo = out + (size_t)row_lo * DIM;
    float* or_hi = out + (size_t)row_hi * DIM;
    #pragma unroll
    for (int nt = 0; nt < 16; nt++) {
        const int c0 = nt * 8 + t * 2;
        const float g0 = gamma[c0], g1 = gamma[c0 + 1];
        const float b0 = beta[c0],  b1 = beta[c0 + 1];
        or_lo[c0]     = (o[nt][0] - mu_lo) * rstd_lo * g0 + b0;
        or_lo[c0 + 1] = (o[nt][1] - mu_lo) * rstd_lo * g1 + b1;
        or_hi[c0]     = (o[nt][2] - mu_hi) * rstd_hi * g0 + b0;
        or_hi[c0 + 1] = (o[nt][3] - mu_hi) * rstd_hi * g1 + b1;
    }
}

// ---------------------------------------------------------------------------
extern "C" void kernel_launch(void* const* d_in, const int* in_sizes, int n_in,
                              void* d_out, int out_size) {
    const float* x     = (const float*)d_in[0];
    const float* gamma = (const float*)d_in[1];
    const float* beta  = (const float*)d_in[2];
    float* out = (float*)d_out;

    cudaFuncSetAttribute(attn_kernel, cudaFuncAttributeMaxDynamicSharedMemorySize,
                         SMEM_TOTAL);

    prep_kernel<<<N_TOK / 8, 256>>>(x);
    attn_kernel<<<NBLK, 256, SMEM_TOTAL>>>(x, gamma, beta, out);
}